// round 15
// baseline (speedup 1.0000x reference)
#include <cuda_runtime.h>
#include <cuda_fp16.h>
#include <cstdint>

#define BB 8192
#define HH 100
#define TT 512
#define NOPSN 5
#define ZW 400
#define MROWS 64
#define NTHREADS 256

// strides (bytes)
#define BSTR 224      // bhi: 112 f16 / row ; B'/A' fp8: 224 bytes (k'=224)

// smem byte offsets
#define SM_BH   0                  // Wh^T f16 hi [400][224]      = 89600
#define SM_B8   89600              // B' fp8      [400][224]      = 89600
#define SM_AH   179200             // h f16 hi    [64][224]       = 14336
#define SM_A8   193536             // A' fp8      [64][224]       = 14336
#define SM_EMB  207872             // float[6*400]                = 9600
#define SM_WOPS 217472             // float[500]                  = 2000
#define SM_PL   219472             // float[64*10]                = 2560
#define SM_OPS  222032             // int[64]                     = 256
#define SM_TOTAL 222288

__device__ float g_xW0[(size_t)BB * ZW];   // x0@Wx, permuted cols
__device__ float g_embW[6 * ZW];           // emb@Wx, permuted cols

// storage col j -> original col (j%4)*100 + j/4 (gate-interleaved)
__device__ __host__ __forceinline__ int permCol(int j) { return (j & 3) * 100 + (j >> 2); }

__device__ __forceinline__ float tanha(float x) {
    float y; asm("tanh.approx.f32 %0, %1;" : "=f"(y) : "f"(x)); return y;
}
__device__ __forceinline__ float fsig(float x) { return fmaf(0.5f, tanha(0.5f * x), 0.5f); }

__device__ __forceinline__ uint32_t smem_u32(const void* p) {
    uint32_t a;
    asm("{ .reg .u64 t; cvta.to.shared.u64 t, %1; cvt.u32.u64 %0, t; }" : "=r"(a) : "l"(p));
    return a;
}
__device__ __forceinline__ unsigned f2e4m3(float x) {
    unsigned short r;
    asm("cvt.rn.satfinite.e4m3x2.f32 %0, %1, %1;" : "=h"(r) : "f"(x));
    return (unsigned)(r & 0xFFu);
}
__device__ __forceinline__ void ldsm4(uint32_t& r0, uint32_t& r1, uint32_t& r2, uint32_t& r3, uint32_t a) {
    asm volatile("ldmatrix.sync.aligned.m8n8.x4.shared.b16 {%0,%1,%2,%3}, [%4];"
                 : "=r"(r0), "=r"(r1), "=r"(r2), "=r"(r3) : "r"(a));
}
__device__ __forceinline__ void ldsm2(uint32_t& r0, uint32_t& r1, uint32_t a) {
    asm volatile("ldmatrix.sync.aligned.m8n8.x2.shared.b16 {%0,%1}, [%2];"
                 : "=r"(r0), "=r"(r1) : "r"(a));
}
__device__ __forceinline__ void mma16816(float& d0, float& d1, float& d2, float& d3,
                                         uint32_t a0, uint32_t a1, uint32_t a2, uint32_t a3,
                                         uint32_t b0, uint32_t b1) {
    asm volatile("mma.sync.aligned.m16n8k16.row.col.f32.f16.f16.f32 "
                 "{%0,%1,%2,%3}, {%4,%5,%6,%7}, {%8,%9}, {%0,%1,%2,%3};"
                 : "+f"(d0), "+f"(d1), "+f"(d2), "+f"(d3)
                 : "r"(a0), "r"(a1), "r"(a2), "r"(a3), "r"(b0), "r"(b1));
}
__device__ __forceinline__ void mma_fp8(float& d0, float& d1, float& d2, float& d3,
                                        uint32_t a0, uint32_t a1, uint32_t a2, uint32_t a3,
                                        uint32_t b0, uint32_t b1) {
    asm volatile("mma.sync.aligned.m16n8k32.row.col.f32.e4m3.e4m3.f32 "
                 "{%0,%1,%2,%3}, {%4,%5,%6,%7}, {%8,%9}, {%0,%1,%2,%3};"
                 : "+f"(d0), "+f"(d1), "+f"(d2), "+f"(d3)
                 : "r"(a0), "r"(a1), "r"(a2), "r"(a3), "r"(b0), "r"(b1));
}
__device__ __forceinline__ void pairbar(int id) {
    asm volatile("bar.sync %0, 64;" :: "r"(id) : "memory");
}

__global__ void embW_kernel(const float* __restrict__ emb, const float* __restrict__ Wx) {
    int j = threadIdx.x;
    if (j >= ZW) return;
    int pj = permCol(j);
    for (int e = 0; e < 6; ++e) {
        float acc = 0.f;
        #pragma unroll 4
        for (int k = 0; k < HH; ++k) acc = fmaf(emb[e * HH + k], Wx[k * ZW + pj], acc);
        g_embW[e * ZW + j] = acc;
    }
}

__global__ void xw0_kernel(const float* __restrict__ x0, const float* __restrict__ Wx) {
    __shared__ float xs[HH];
    int b = blockIdx.x;
    for (int i = threadIdx.x; i < HH; i += blockDim.x) xs[i] = x0[b * HH + i];
    __syncthreads();
    for (int j = threadIdx.x; j < ZW; j += blockDim.x) {
        int pj = permCol(j);
        float acc = 0.f;
        #pragma unroll 4
        for (int k = 0; k < HH; ++k) acc = fmaf(xs[k], Wx[k * ZW + pj], acc);
        g_xW0[(size_t)b * ZW + j] = acc;
    }
}

__global__ void __launch_bounds__(NTHREADS, 1)
rnn_main(const float* __restrict__ Wh, const float* __restrict__ Wops,
         const float* __restrict__ upt, float* __restrict__ out)
{
    extern __shared__ char smb[];
    const uint32_t sb = smem_u32(smb);
    float* sEmbF = (float*)(smb + SM_EMB);
    float* sWops = (float*)(smb + SM_WOPS);
    float* sPL   = (float*)(smb + SM_PL);
    int*   sOps  = (int*)(smb + SM_OPS);

    const int tid = threadIdx.x, wid = tid >> 5, lane = tid & 31;

    // ---- one-time init ----
    // bhi: Wh^T f16 hi, k 0..111 (zeros >= 100)
    for (int idx = tid; idx < 400 * 112; idx += NTHREADS) {
        int n = idx / 112, k = idx - n * 112;
        float w = (k < HH) ? Wh[k * ZW + permCol(n)] : 0.f;
        *(__half*)(smb + SM_BH + n * BSTR + k * 2) = __float2half_rn(w);
    }
    // B' fp8: k' 0..99 = e4m3(4096*(W - f16(W))) ; 112..211 = e4m3(W) ; else 0
    for (int idx = tid; idx < 400 * 224; idx += NTHREADS) {
        int n = idx / 224, k2 = idx - n * 224;
        float v = 0.f;
        if (k2 < HH) {
            float w = Wh[k2 * ZW + permCol(n)];
            v = (w - __half2float(__float2half_rn(w))) * 4096.f;
        } else if (k2 >= 112 && k2 < 112 + HH) {
            v = Wh[(k2 - 112) * ZW + permCol(n)];
        }
        ((unsigned char*)smb)[SM_B8 + n * BSTR + k2] = (unsigned char)f2e4m3(v);
    }
    // zero A stages (h(-1) = 0)
    for (int i = tid; i < (MROWS * BSTR) / 4; i += NTHREADS) {
        ((uint32_t*)(smb + SM_AH))[i] = 0u;
        ((uint32_t*)(smb + SM_A8))[i] = 0u;
    }
    for (int i = tid; i < 6 * ZW; i += NTHREADS) sEmbF[i] = g_embW[i];
    for (int i = tid; i < HH * NOPSN; i += NTHREADS) sWops[i] = Wops[i];
    __syncthreads();

    const int mt = wid & 3, nh = wid >> 2;
    const int gr = lane >> 2, cq = lane & 3;
    const bool even = ((lane & 1) == 0);
    const int m0 = mt * 16;
    const int R0l = m0 + gr, R1l = R0l + 8;
    const int jbase = nh * 25;
    const int barid = 1 + mt;
    const bool epi = (lane < 8);
    const int erow = m0 + nh * 8 + (lane & 7);

    // ldsm lane addressing
    const int lr = lane & 7, gg = lane >> 3;
    const uint32_t aAddrHi = sb + SM_AH + (uint32_t)(m0 + lr + (gg & 1) * 8) * BSTR + (gg >> 1) * 16;
    const uint32_t bOffH = (uint32_t)lr * BSTR + (gg & 1) * 16;
    // fp8 A-frag rows for this lane
    const int rA = m0 + gr, rB = m0 + gr + 8;

    float cS[25];
    #pragma unroll
    for (int i = 0; i < 25; ++i) cS[i] = 0.f;
    float accLP = 0.f, accENT = 0.f;

    for (int t = 0; t < TT; ++t) {
        float un[NOPSN];
        if (epi) {
            const float* up = upt + ((size_t)t * BB + blockIdx.x * MROWS + erow) * NOPSN;
            #pragma unroll
            for (int n = 0; n < NOPSN; ++n) un[n] = up[n];
        }

        pairbar(barid);   // bar0: h(t-1) stages + sOps(t-1) stable

        const float *p0, *p1;
        if (t == 0) {
            p0 = g_xW0 + (size_t)(blockIdx.x * MROWS + R0l) * ZW;
            p1 = g_xW0 + (size_t)(blockIdx.x * MROWS + R1l) * ZW;
        } else {
            p0 = sEmbF + sOps[R0l] * ZW;
            p1 = sEmbF + sOps[R1l] * ZW;
        }

        // ---- load A fragments: f16 hi (ldsm) + fp8 A' (LDS.32) ----
        uint32_t ahi[28], af8[28];
        #pragma unroll
        for (int kk = 0; kk < 7; ++kk) {
            ldsm4(ahi[4 * kk], ahi[4 * kk + 1], ahi[4 * kk + 2], ahi[4 * kk + 3], aAddrHi + kk * 32);
            af8[4 * kk + 0] = *(const uint32_t*)(smb + SM_A8 + rA * BSTR + kk * 32 + 4 * cq);
            af8[4 * kk + 1] = *(const uint32_t*)(smb + SM_A8 + rB * BSTR + kk * 32 + 4 * cq);
            af8[4 * kk + 2] = *(const uint32_t*)(smb + SM_A8 + rA * BSTR + kk * 32 + 16 + 4 * cq);
            af8[4 * kk + 3] = *(const uint32_t*)(smb + SM_A8 + rB * BSTR + kk * 32 + 16 + 4 * cq);
        }
        pairbar(barid);   // bar1: slab A reads done; safe to overwrite with h(t)

        float pl[NOPSN] = {0.f, 0.f, 0.f, 0.f, 0.f};

        #pragma unroll
        for (int jj = 0; jj < 25; ++jj) {
            const int n0 = 8 * (jbase + jj);
            const uint32_t bbH = sb + SM_BH + (uint32_t)n0 * BSTR + bOffH;
            const char* bb8 = smb + SM_B8 + (n0 + (lane >> 2)) * BSTR + 4 * cq;

            float A0 = 0.f, A1 = 0.f, A2 = 0.f, A3 = 0.f;   // pass A (f16 hi·hi)
            float C0 = 0.f, C1 = 0.f, C2 = 0.f, C3 = 0.f;   // fp8 corrections (x4096)
            #pragma unroll
            for (int kk = 0; kk < 7; ++kk) {
                uint32_t bh0, bh1;
                ldsm2(bh0, bh1, bbH + kk * 32);
                mma16816(A0, A1, A2, A3, ahi[4 * kk], ahi[4 * kk + 1], ahi[4 * kk + 2], ahi[4 * kk + 3], bh0, bh1);
                uint32_t c0 = *(const uint32_t*)(bb8 + kk * 32);
                uint32_t c1 = *(const uint32_t*)(bb8 + kk * 32 + 16);
                mma_fp8(C0, C1, C2, C3, af8[4 * kk], af8[4 * kk + 1], af8[4 * kk + 2], af8[4 * kk + 3], c0, c1);
            }
            const int col0 = n0 + 2 * cq;
            const float S = 1.f / 4096.f;
            float z0 = (A0 + C0 * S) + p0[col0];
            float z1 = (A1 + C1 * S) + p0[col0 + 1];
            float z2 = (A2 + C2 * S) + p1[col0];
            float z3 = (A3 + C3 * S) + p1[col0 + 1];
            float o0 = __shfl_xor_sync(0xffffffffu, z0, 1);
            float o1 = __shfl_xor_sync(0xffffffffu, z1, 1);
            float o2 = __shfl_xor_sync(0xffffffffu, z2, 1);
            float o3 = __shfl_xor_sync(0xffffffffu, z3, 1);
            float zi = even ? z0 : o2;
            float zf = even ? z1 : o3;
            float zc = even ? o0 : z2;
            float zo = even ? o1 : z3;
            float cn = fsig(zf) * cS[jj] + fsig(zi) * tanha(zc);
            cS[jj] = cn;
            float hn = fsig(zo) * tanha(cn);
            const int u = 2 * (jbase + jj) + (cq >> 1);
            const int myrow = even ? R0l : R1l;
            __half hh = __float2half_rn(hn);
            *(__half*)(smb + SM_AH + myrow * BSTR + u * 2) = hh;
            unsigned char* a8p = (unsigned char*)(smb + SM_A8 + myrow * BSTR);
            a8p[u] = (unsigned char)f2e4m3(hn);
            a8p[112 + u] = (unsigned char)f2e4m3((hn - __half2float(hh)) * 4096.f);
            const float* wp = sWops + u * NOPSN;
            pl[0] = fmaf(hn, wp[0], pl[0]);
            pl[1] = fmaf(hn, wp[1], pl[1]);
            pl[2] = fmaf(hn, wp[2], pl[2]);
            pl[3] = fmaf(hn, wp[3], pl[3]);
            pl[4] = fmaf(hn, wp[4], pl[4]);
        }

        #pragma unroll
        for (int n = 0; n < NOPSN; ++n)
            pl[n] += __shfl_xor_sync(0xffffffffu, pl[n], 2);
        if (cq < 2) {
            int rw = (cq == 0) ? R0l : R1l;
            #pragma unroll
            for (int n = 0; n < NOPSN; ++n)
                sPL[rw * 10 + nh * NOPSN + n] = pl[n];
        }
        pairbar(barid);   // bar2: slab sPL + h(t) complete

        if (epi) {
            int b = blockIdx.x * MROWS + erow;
            float lg[NOPSN];
            #pragma unroll
            for (int n = 0; n < NOPSN; ++n) {
                float s = sPL[erow * 10 + n] + sPL[erow * 10 + NOPSN + n];
                lg[n] = 1.5f * tanhf(s);
            }
            int op = 0;
            float best = 0.f, mx = lg[0], lsel = lg[0];
            #pragma unroll
            for (int n = 0; n < NOPSN; ++n) {
                float gum = -logf(-logf(un[n] + 1e-9f) + 1e-9f);
                float v = lg[n] + gum;
                if (n == 0) { best = v; }
                else if (v > best) { best = v; op = n; lsel = lg[n]; }
                if (lg[n] > mx) mx = lg[n];
            }
            float ss = 0.f;
            #pragma unroll
            for (int n = 0; n < NOPSN; ++n) ss += expf(lg[n] - mx);
            float lse = mx + logf(ss);
            float cur = lse - lsel;
            float ent = cur * expf(-cur);
            accLP += cur; accENT += ent;
            sOps[erow] = op;
            out[2 * (size_t)BB + (size_t)t * BB + b] = (float)op;
        }
    }

    if (epi) {
        int b = blockIdx.x * MROWS + erow;
        out[b] = accLP;
        out[BB + b] = accENT;
    }
}

extern "C" void kernel_launch(void* const* d_in, const int* in_sizes, int n_in,
                              void* d_out, int out_size) {
    const float* x0  = (const float*)d_in[0];
    const float* Wx  = (const float*)d_in[1];
    const float* Wh  = (const float*)d_in[2];
    const float* Wop = (const float*)d_in[3];
    const float* emb = (const float*)d_in[4];
    const float* u   = (const float*)d_in[5];
    float* out = (float*)d_out;

    cudaFuncSetAttribute(rnn_main, cudaFuncAttributeMaxDynamicSharedMemorySize, SM_TOTAL);

    embW_kernel<<<1, ZW>>>(emb, Wx);
    xw0_kernel<<<BB, 128>>>(x0, Wx);
    rnn_main<<<BB / MROWS, NTHREADS, SM_TOTAL>>>(Wh, Wop, u, out);
}

// round 16
// speedup vs baseline: 1.4865x; 1.4865x over previous
#include <cuda_runtime.h>
#include <cuda_fp16.h>
#include <cstdint>

#define BB 8192
#define HH 100
#define TT 512
#define NOPSN 5
#define ZW 400
#define MROWS 64
#define NTHREADS 512
#define RSTRIDE 464   // bytes/row: 112 f16 hi (224B) + 112 f16 lo (224B) + 16B pad

// smem byte offsets
#define SM_B    0                  // WhT hi/lo  [400][464]       = 185600
#define SM_A    185600             // h stage    [64][464]        = 29696
#define SM_EMB  215296             // float[6*400]                = 9600
#define SM_WOPS 224896             // float[500]                  = 2000
#define SM_PL   226896             // float[64*20]                = 5120
#define SM_OPS  232016             // int[64]                     = 256
#define SM_TOTAL 232272

__device__ float g_xW0[(size_t)BB * ZW];   // x0@Wx, permuted cols
__device__ float g_embW[6 * ZW];           // emb@Wx, permuted cols

// storage col j -> original col (j%4)*100 + j/4 (gate-interleaved)
__device__ __host__ __forceinline__ int permCol(int j) { return (j & 3) * 100 + (j >> 2); }

__device__ __forceinline__ float tanha(float x) {
    float y; asm("tanh.approx.f32 %0, %1;" : "=f"(y) : "f"(x)); return y;
}
__device__ __forceinline__ float fsig(float x) { return fmaf(0.5f, tanha(0.5f * x), 0.5f); }

__device__ __forceinline__ uint32_t smem_u32(const void* p) {
    uint32_t a;
    asm("{ .reg .u64 t; cvta.to.shared.u64 t, %1; cvt.u32.u64 %0, t; }" : "=r"(a) : "l"(p));
    return a;
}
__device__ __forceinline__ void ldsm4(uint32_t& r0, uint32_t& r1, uint32_t& r2, uint32_t& r3, uint32_t a) {
    asm volatile("ldmatrix.sync.aligned.m8n8.x4.shared.b16 {%0,%1,%2,%3}, [%4];"
                 : "=r"(r0), "=r"(r1), "=r"(r2), "=r"(r3) : "r"(a));
}
__device__ __forceinline__ void mma16816(float& d0, float& d1, float& d2, float& d3,
                                         uint32_t a0, uint32_t a1, uint32_t a2, uint32_t a3,
                                         uint32_t b0, uint32_t b1) {
    asm volatile("mma.sync.aligned.m16n8k16.row.col.f32.f16.f16.f32 "
                 "{%0,%1,%2,%3}, {%4,%5,%6,%7}, {%8,%9}, {%0,%1,%2,%3};"
                 : "+f"(d0), "+f"(d1), "+f"(d2), "+f"(d3)
                 : "r"(a0), "r"(a1), "r"(a2), "r"(a3), "r"(b0), "r"(b1));
}
// f16-accumulator variant: D,C are 2 x .f16x2 regs
__device__ __forceinline__ void mma16816h(uint32_t& d0, uint32_t& d1,
                                          uint32_t a0, uint32_t a1, uint32_t a2, uint32_t a3,
                                          uint32_t b0, uint32_t b1) {
    asm volatile("mma.sync.aligned.m16n8k16.row.col.f16.f16.f16.f16 "
                 "{%0,%1}, {%2,%3,%4,%5}, {%6,%7}, {%0,%1};"
                 : "+r"(d0), "+r"(d1)
                 : "r"(a0), "r"(a1), "r"(a2), "r"(a3), "r"(b0), "r"(b1));
}
__device__ __forceinline__ void slabbar(int id) {
    asm volatile("bar.sync %0, 128;" :: "r"(id) : "memory");
}
__device__ __forceinline__ float2 h2f2(uint32_t v) {
    __half2 h = *reinterpret_cast<__half2*>(&v);
    return __half22float2(h);
}

__global__ void embW_kernel(const float* __restrict__ emb, const float* __restrict__ Wx) {
    int j = threadIdx.x;
    if (j >= ZW) return;
    int pj = permCol(j);
    for (int e = 0; e < 6; ++e) {
        float acc = 0.f;
        #pragma unroll 4
        for (int k = 0; k < HH; ++k) acc = fmaf(emb[e * HH + k], Wx[k * ZW + pj], acc);
        g_embW[e * ZW + j] = acc;
    }
}

__global__ void xw0_kernel(const float* __restrict__ x0, const float* __restrict__ Wx) {
    __shared__ float xs[HH];
    int b = blockIdx.x;
    for (int i = threadIdx.x; i < HH; i += blockDim.x) xs[i] = x0[b * HH + i];
    __syncthreads();
    for (int j = threadIdx.x; j < ZW; j += blockDim.x) {
        int pj = permCol(j);
        float acc = 0.f;
        #pragma unroll 4
        for (int k = 0; k < HH; ++k) acc = fmaf(xs[k], Wx[k * ZW + pj], acc);
        g_xW0[(size_t)b * ZW + j] = acc;
    }
}

__global__ void __launch_bounds__(NTHREADS, 1)
rnn_main(const float* __restrict__ Wh, const float* __restrict__ Wops,
         const float* __restrict__ upt, float* __restrict__ out)
{
    extern __shared__ char smb[];
    const uint32_t sb = smem_u32(smb);
    float* sEmbF = (float*)(smb + SM_EMB);
    float* sWops = (float*)(smb + SM_WOPS);
    float* sPL   = (float*)(smb + SM_PL);
    int*   sOps  = (int*)(smb + SM_OPS);

    const int tid = threadIdx.x, wid = tid >> 5, lane = tid & 31;

    // ---- one-time init: B = Wh^T as f16 hi/lo, gate-interleaved n, K padded to 112 ----
    for (int idx = tid; idx < 400 * 112; idx += NTHREADS) {
        int n = idx / 112, k = idx - n * 112;
        float w = (k < HH) ? Wh[k * ZW + permCol(n)] : 0.f;
        __half hh = __float2half_rn(w);
        __half hl = __float2half_rn(w - __half2float(hh));
        *(__half*)(smb + SM_B + n * RSTRIDE + k * 2) = hh;
        *(__half*)(smb + SM_B + n * RSTRIDE + 224 + k * 2) = hl;
    }
    // zero A stage (h(-1) = 0, incl. k-pad 100..111)
    for (int i = tid; i < (MROWS * RSTRIDE) / 4; i += NTHREADS)
        ((uint32_t*)(smb + SM_A))[i] = 0u;
    for (int i = tid; i < 6 * ZW; i += NTHREADS) sEmbF[i] = g_embW[i];
    for (int i = tid; i < HH * NOPSN; i += NTHREADS) sWops[i] = Wops[i];
    __syncthreads();

    const int mt = wid & 3;           // row slab (16 rows)
    const int nq = wid >> 2;          // n quarter (0..3)
    const int gr = lane >> 2, cq = lane & 3;
    const bool even = ((lane & 1) == 0);
    const int m0 = mt * 16;
    const int R0l = m0 + gr, R1l = R0l + 8;
    const int jcnt   = (nq < 2) ? 13 : 12;
    const int jstart = (nq < 2) ? 13 * nq : 26 + 12 * (nq - 2);
    const int barid = 1 + mt;
    // epilogue: warp nq of the slab covers rows m0 + 4*nq .. +3 (lanes 0..3)
    const bool epi = (lane < 4);
    const int erow = m0 + nq * 4 + (lane & 3);

    // A-frag lane addressing (ldmatrix x4 groups)
    const int lr = lane & 7, gg = lane >> 3;
    const uint32_t aAddrHi = sb + SM_A + (uint32_t)(m0 + lr + (gg & 1) * 8) * RSTRIDE + (gg >> 1) * 16;
    // B-frag lane addressing: groups = {hi k0, hi k0+8, lo k0, lo k0+8}
    const uint32_t bOffLane = (uint32_t)lr * RSTRIDE + (gg & 1) * 16 + (gg >> 1) * 224;

    float cS[13];
    #pragma unroll
    for (int i = 0; i < 13; ++i) cS[i] = 0.f;
    float accLP = 0.f, accENT = 0.f;

    for (int t = 0; t < TT; ++t) {
        // gumbel inputs for this lane's epilogue row
        float un[NOPSN];
        if (epi) {
            const float* up = upt + ((size_t)t * BB + blockIdx.x * MROWS + erow) * NOPSN;
            #pragma unroll
            for (int n = 0; n < NOPSN; ++n) un[n] = up[n];
        }

        slabbar(barid);   // bar0: h(t-1) stage + sOps(t-1) stable for this slab

        // per-row xW pointers
        const float *p0, *p1;
        if (t == 0) {
            p0 = g_xW0 + (size_t)(blockIdx.x * MROWS + R0l) * ZW;
            p1 = g_xW0 + (size_t)(blockIdx.x * MROWS + R1l) * ZW;
        } else {
            p0 = sEmbF + sOps[R0l] * ZW;
            p1 = sEmbF + sOps[R1l] * ZW;
        }

        // ---- load A fragments (h(t-1) hi/lo), 7 k-steps ----
        uint32_t ahi[28], alo[28];
        #pragma unroll
        for (int kk = 0; kk < 7; ++kk) {
            ldsm4(ahi[4 * kk], ahi[4 * kk + 1], ahi[4 * kk + 2], ahi[4 * kk + 3], aAddrHi + kk * 32);
            ldsm4(alo[4 * kk], alo[4 * kk + 1], alo[4 * kk + 2], alo[4 * kk + 3], aAddrHi + 224 + kk * 32);
        }
        slabbar(barid);   // bar1: slab A reads done; safe to overwrite with h(t)

        float pl[NOPSN] = {0.f, 0.f, 0.f, 0.f, 0.f};

        #pragma unroll
        for (int jj = 0; jj < 13; ++jj) {
            if (jj >= jcnt) break;
            const int tile = jstart + jj;
            const int n0 = 8 * tile;
            const uint32_t bb = sb + SM_B + (uint32_t)n0 * RSTRIDE + bOffLane;
            // pass A: f32 accumulate (full magnitude); passes B,C: f16 accumulate (corrections)
            float A0 = 0.f, A1 = 0.f, A2 = 0.f, A3 = 0.f;
            uint32_t Bh0 = 0u, Bh1 = 0u;   // ahi*blo
            uint32_t Ch0 = 0u, Ch1 = 0u;   // alo*bhi
            #pragma unroll
            for (int kk = 0; kk < 7; ++kk) {
                uint32_t bh0, bh1, bl0, bl1;
                ldsm4(bh0, bh1, bl0, bl1, bb + kk * 32);
                mma16816(A0, A1, A2, A3, ahi[4 * kk], ahi[4 * kk + 1], ahi[4 * kk + 2], ahi[4 * kk + 3], bh0, bh1);
                mma16816h(Bh0, Bh1, ahi[4 * kk], ahi[4 * kk + 1], ahi[4 * kk + 2], ahi[4 * kk + 3], bl0, bl1);
                mma16816h(Ch0, Ch1, alo[4 * kk], alo[4 * kk + 1], alo[4 * kk + 2], alo[4 * kk + 3], bh0, bh1);
            }
            const int col0 = n0 + 2 * cq;
            float2 b0f = h2f2(Bh0), b1f = h2f2(Bh1);
            float2 c0f = h2f2(Ch0), c1f = h2f2(Ch1);
            float z0 = (A0 + b0f.x + c0f.x) + p0[col0];
            float z1 = (A1 + b0f.y + c0f.y) + p0[col0 + 1];
            float z2 = (A2 + b1f.x + c1f.x) + p1[col0];
            float z3 = (A3 + b1f.y + c1f.y) + p1[col0 + 1];
            float o0 = __shfl_xor_sync(0xffffffffu, z0, 1);
            float o1 = __shfl_xor_sync(0xffffffffu, z1, 1);
            float o2 = __shfl_xor_sync(0xffffffffu, z2, 1);
            float o3 = __shfl_xor_sync(0xffffffffu, z3, 1);
            // even lane: row R0 gates (i,f)=own(z0,z1), (c,o)=partner(o0,o1)
            // odd  lane: row R1 gates (i,f)=partner(o2,o3), (c,o)=own(z2,z3)
            float zi = even ? z0 : o2;
            float zf = even ? z1 : o3;
            float zc = even ? o0 : z2;
            float zo = even ? o1 : z3;
            float cn = fsig(zf) * cS[jj] + fsig(zi) * tanha(zc);
            cS[jj] = cn;
            float hn = fsig(zo) * tanha(cn);
            const int u = 2 * tile + (cq >> 1);
            const int myrow = even ? R0l : R1l;
            __half hh = __float2half_rn(hn);
            __half hl = __float2half_rn(hn - __half2float(hh));
            *(__half*)(smb + SM_A + myrow * RSTRIDE + u * 2) = hh;
            *(__half*)(smb + SM_A + myrow * RSTRIDE + 224 + u * 2) = hl;
            const float* wp = sWops + u * NOPSN;
            pl[0] = fmaf(hn, wp[0], pl[0]);
            pl[1] = fmaf(hn, wp[1], pl[1]);
            pl[2] = fmaf(hn, wp[2], pl[2]);
            pl[3] = fmaf(hn, wp[3], pl[3]);
            pl[4] = fmaf(hn, wp[4], pl[4]);
        }

        // combine unit-partials within warp: lanes {4g,4g+2} -> row R0, {4g+1,4g+3} -> row R1
        #pragma unroll
        for (int n = 0; n < NOPSN; ++n)
            pl[n] += __shfl_xor_sync(0xffffffffu, pl[n], 2);
        if (cq < 2) {
            int rw = (cq == 0) ? R0l : R1l;
            #pragma unroll
            for (int n = 0; n < NOPSN; ++n)
                sPL[rw * 20 + nq * NOPSN + n] = pl[n];
        }
        slabbar(barid);   // bar2: slab sPL + h(t) complete

        // ---- sampling / log-softmax epilogue (accurate libm; 4 lanes per warp) ----
        if (epi) {
            int b = blockIdx.x * MROWS + erow;
            float lg[NOPSN];
            #pragma unroll
            for (int n = 0; n < NOPSN; ++n) {
                float s = sPL[erow * 20 + n] + sPL[erow * 20 + 5 + n]
                        + sPL[erow * 20 + 10 + n] + sPL[erow * 20 + 15 + n];
                lg[n] = 1.5f * tanhf(s);
            }
            int op = 0;
            float best = 0.f, mx = lg[0], lsel = lg[0];
            #pragma unroll
            for (int n = 0; n < NOPSN; ++n) {
                float gum = -logf(-logf(un[n] + 1e-9f) + 1e-9f);
                float v = lg[n] + gum;
                if (n == 0) { best = v; }
                else if (v > best) { best = v; op = n; lsel = lg[n]; }
                if (lg[n] > mx) mx = lg[n];
            }
            float ss = 0.f;
            #pragma unroll
            for (int n = 0; n < NOPSN; ++n) ss += expf(lg[n] - mx);
            float lse = mx + logf(ss);
            float cur = lse - lsel;
            float ent = cur * expf(-cur);
            accLP += cur; accENT += ent;
            sOps[erow] = op;
            out[2 * (size_t)BB + (size_t)t * BB + b] = (float)op;
        }
    }

    if (epi) {
        int b = blockIdx.x * MROWS + erow;
        out[b] = accLP;
        out[BB + b] = accENT;
    }
}

extern "C" void kernel_launch(void* const* d_in, const int* in_sizes, int n_in,
                              void* d_out, int out_size) {
    const float* x0  = (const float*)d_in[0];
    const float* Wx  = (const float*)d_in[1];
    const float* Wh  = (const float*)d_in[2];
    const float* Wop = (const float*)d_in[3];
    const float* emb = (const float*)d_in[4];
    const float* u   = (const float*)d_in[5];
    float* out = (float*)d_out;

    cudaFuncSetAttribute(rnn_main, cudaFuncAttributeMaxDynamicSharedMemorySize, SM_TOTAL);

    embW_kernel<<<1, ZW>>>(emb, Wx);
    xw0_kernel<<<BB, 128>>>(x0, Wx);
    rnn_main<<<BB / MROWS, NTHREADS, SM_TOTAL>>>(Wh, Wop, u, out);
}

// round 17
// speedup vs baseline: 1.5382x; 1.0348x over previous
#include <cuda_runtime.h>
#include <cuda_fp16.h>
#include <cstdint>

#define BB 8192
#define HH 100
#define TT 512
#define NOPSN 5
#define ZW 400
#define MROWS 64
#define NTHREADS 256
#define RSTRIDE 464   // bytes/row: 112 f16 hi (224B) + 112 f16 lo (224B) + 16B pad

// steady-state smem layout (bytes)
#define SM_B    0                  // WhT hi/lo  [400][464]       = 185600
#define SM_A    185600             // h stage    [64][464]        = 29696
#define SM_EMB  215296             // float[6*400]                = 9600
#define SM_WOPS 224896             // float[500]                  = 2000
#define SM_PL   226896             // float[64*10]                = 2560
#define SM_OPS  229456             // int[64]                     = 256
#define SM_TOTAL 229712
// pre-phase overlay (same buffer): sWx f32[100*400] @0 (160000), xs f32[72*100] @160000 (28800)
#define PP_WX   0
#define PP_XS   160000

__device__ float g_xW0[(size_t)BB * ZW];   // x0@Wx, permuted cols

// storage col j -> original col (j%4)*100 + j/4 (gate-interleaved)
__device__ __host__ __forceinline__ int permCol(int j) { return (j & 3) * 100 + (j >> 2); }

__device__ __forceinline__ float tanha(float x) {
    float y; asm("tanh.approx.f32 %0, %1;" : "=f"(y) : "f"(x)); return y;
}
__device__ __forceinline__ float fsig(float x) { return fmaf(0.5f, tanha(0.5f * x), 0.5f); }

__device__ __forceinline__ uint32_t smem_u32(const void* p) {
    uint32_t a;
    asm("{ .reg .u64 t; cvta.to.shared.u64 t, %1; cvt.u32.u64 %0, t; }" : "=r"(a) : "l"(p));
    return a;
}
__device__ __forceinline__ void ldsm4(uint32_t& r0, uint32_t& r1, uint32_t& r2, uint32_t& r3, uint32_t a) {
    asm volatile("ldmatrix.sync.aligned.m8n8.x4.shared.b16 {%0,%1,%2,%3}, [%4];"
                 : "=r"(r0), "=r"(r1), "=r"(r2), "=r"(r3) : "r"(a));
}
// NOTE: mma wrappers are NON-volatile pure register ops — lets ptxas software-pipeline
__device__ __forceinline__ void mma16816(float& d0, float& d1, float& d2, float& d3,
                                         uint32_t a0, uint32_t a1, uint32_t a2, uint32_t a3,
                                         uint32_t b0, uint32_t b1) {
    asm("mma.sync.aligned.m16n8k16.row.col.f32.f16.f16.f32 "
        "{%0,%1,%2,%3}, {%4,%5,%6,%7}, {%8,%9}, {%0,%1,%2,%3};"
        : "+f"(d0), "+f"(d1), "+f"(d2), "+f"(d3)
        : "r"(a0), "r"(a1), "r"(a2), "r"(a3), "r"(b0), "r"(b1));
}
__device__ __forceinline__ void mma16816h(uint32_t& d0, uint32_t& d1,
                                          uint32_t a0, uint32_t a1, uint32_t a2, uint32_t a3,
                                          uint32_t b0, uint32_t b1) {
    asm("mma.sync.aligned.m16n8k16.row.col.f16.f16.f16.f16 "
        "{%0,%1}, {%2,%3,%4,%5}, {%6,%7}, {%0,%1};"
        : "+r"(d0), "+r"(d1)
        : "r"(a0), "r"(a1), "r"(a2), "r"(a3), "r"(b0), "r"(b1));
}
__device__ __forceinline__ void pairbar(int id) {
    asm volatile("bar.sync %0, 64;" :: "r"(id) : "memory");
}
__device__ __forceinline__ float2 h2f2(uint32_t v) {
    __half2 h = *reinterpret_cast<__half2*>(&v);
    return __half22float2(h);
}

__global__ void __launch_bounds__(NTHREADS, 1)
rnn_main(const float* __restrict__ Wh, const float* __restrict__ Wops,
         const float* __restrict__ upt, float* __restrict__ out,
         const float* __restrict__ x0, const float* __restrict__ Wx,
         const float* __restrict__ emb)
{
    extern __shared__ char smb[];
    const uint32_t sb = smem_u32(smb);
    float* sEmbF = (float*)(smb + SM_EMB);
    float* sWops = (float*)(smb + SM_WOPS);
    float* sPL   = (float*)(smb + SM_PL);
    int*   sOps  = (int*)(smb + SM_OPS);

    const int tid = threadIdx.x, wid = tid >> 5, lane = tid & 31;

    // ================= pre-phase: x0@Wx (this block's 64 rows) + emb@Wx =================
    {
        float* sWx = (float*)(smb + PP_WX);   // [100][400] permuted cols
        float* xs  = (float*)(smb + PP_XS);   // [72][100]: rows 0..63 = x0, 64..69 = emb, 70..71 = 0
        for (int i = tid; i < HH * ZW; i += NTHREADS) {
            int k = i / ZW, j = i - k * ZW;
            sWx[i] = Wx[k * ZW + permCol(j)];
        }
        const int rb = blockIdx.x * MROWS;
        for (int i = tid; i < 72 * HH; i += NTHREADS) {
            int r = i / HH, k = i - r * HH;
            float v = 0.f;
            if (r < 64) v = x0[(size_t)(rb + r) * HH + k];
            else if (r < 70) v = emb[(r - 64) * HH + k];
            xs[i] = v;
        }
        __syncthreads();
        const int j1 = tid, j2 = tid + 256;
        const bool has2 = (j2 < ZW);
        for (int c = 0; c < 9; ++c) {
            float a1[8], a2[8];
            #pragma unroll
            for (int r = 0; r < 8; ++r) { a1[r] = 0.f; a2[r] = 0.f; }
            for (int k = 0; k < HH; ++k) {
                float w1 = sWx[k * ZW + j1];
                float w2 = has2 ? sWx[k * ZW + j2] : 0.f;
                #pragma unroll
                for (int r = 0; r < 8; ++r) {
                    float xv = xs[(c * 8 + r) * HH + k];
                    a1[r] = fmaf(xv, w1, a1[r]);
                    a2[r] = fmaf(xv, w2, a2[r]);
                }
            }
            #pragma unroll
            for (int r = 0; r < 8; ++r) {
                int row = c * 8 + r;
                if (row < 64) {
                    g_xW0[(size_t)(rb + row) * ZW + j1] = a1[r];
                    if (has2) g_xW0[(size_t)(rb + row) * ZW + j2] = a2[r];
                } else if (row < 70) {
                    sEmbF[(row - 64) * ZW + j1] = a1[r];
                    if (has2) sEmbF[(row - 64) * ZW + j2] = a2[r];
                }
            }
        }
        __syncthreads();
    }

    // ================= steady-state init: B = Wh^T f16 hi/lo, zero A, sWops =================
    for (int idx = tid; idx < 400 * 112; idx += NTHREADS) {
        int n = idx / 112, k = idx - n * 112;
        float w = (k < HH) ? Wh[k * ZW + permCol(n)] : 0.f;
        __half hh = __float2half_rn(w);
        __half hl = __float2half_rn(w - __half2float(hh));
        *(__half*)(smb + SM_B + n * RSTRIDE + k * 2) = hh;
        *(__half*)(smb + SM_B + n * RSTRIDE + 224 + k * 2) = hl;
    }
    for (int i = tid; i < (MROWS * RSTRIDE) / 4; i += NTHREADS)
        ((uint32_t*)(smb + SM_A))[i] = 0u;
    for (int i = tid; i < HH * NOPSN; i += NTHREADS) sWops[i] = Wops[i];
    __syncthreads();

    const int mt = wid & 3, nh = wid >> 2;
    const int gr = lane >> 2, cq = lane & 3;
    const bool even = ((lane & 1) == 0);
    const int m0 = mt * 16;
    const int R0l = m0 + gr, R1l = R0l + 8;
    const int jbase = nh * 25;
    const int barid = 1 + mt;
    const bool epi = (lane < 8);
    const int erow = m0 + nh * 8 + (lane & 7);

    const int lr = lane & 7, gg = lane >> 3;
    const uint32_t aAddrHi = sb + SM_A + (uint32_t)(m0 + lr + (gg & 1) * 8) * RSTRIDE + (gg >> 1) * 16;
    const uint32_t bOffLane = (uint32_t)lr * RSTRIDE + (gg & 1) * 16 + (gg >> 1) * 224;

    float cS[25];
    #pragma unroll
    for (int i = 0; i < 25; ++i) cS[i] = 0.f;
    float accLP = 0.f, accENT = 0.f;

    for (int t = 0; t < TT; ++t) {
        float un[NOPSN];
        if (epi) {
            const float* up = upt + ((size_t)t * BB + blockIdx.x * MROWS + erow) * NOPSN;
            #pragma unroll
            for (int n = 0; n < NOPSN; ++n) un[n] = up[n];
        }

        pairbar(barid);   // bar0: h(t-1) stage + sOps(t-1) stable for this slab

        const float *p0, *p1;
        if (t == 0) {
            p0 = g_xW0 + (size_t)(blockIdx.x * MROWS + R0l) * ZW;
            p1 = g_xW0 + (size_t)(blockIdx.x * MROWS + R1l) * ZW;
        } else {
            p0 = sEmbF + sOps[R0l] * ZW;
            p1 = sEmbF + sOps[R1l] * ZW;
        }

        // ---- load A fragments (h(t-1) hi/lo), 7 k-steps ----
        uint32_t ahi[28], alo[28];
        #pragma unroll
        for (int kk = 0; kk < 7; ++kk) {
            ldsm4(ahi[4 * kk], ahi[4 * kk + 1], ahi[4 * kk + 2], ahi[4 * kk + 3], aAddrHi + kk * 32);
            ldsm4(alo[4 * kk], alo[4 * kk + 1], alo[4 * kk + 2], alo[4 * kk + 3], aAddrHi + 224 + kk * 32);
        }
        pairbar(barid);   // bar1: slab A reads done; safe to overwrite with h(t)

        float pl[NOPSN] = {0.f, 0.f, 0.f, 0.f, 0.f};

        #pragma unroll
        for (int jj = 0; jj < 25; ++jj) {
            const int n0 = 8 * (jbase + jj);
            const uint32_t bb = sb + SM_B + (uint32_t)n0 * RSTRIDE + bOffLane;
            float A0 = 0.f, A1 = 0.f, A2 = 0.f, A3 = 0.f;
            uint32_t Bh0 = 0u, Bh1 = 0u;
            uint32_t Ch0 = 0u, Ch1 = 0u;
            #pragma unroll
            for (int kk = 0; kk < 7; ++kk) {
                uint32_t bh0, bh1, bl0, bl1;
                ldsm4(bh0, bh1, bl0, bl1, bb + kk * 32);
                mma16816(A0, A1, A2, A3, ahi[4 * kk], ahi[4 * kk + 1], ahi[4 * kk + 2], ahi[4 * kk + 3], bh0, bh1);
                mma16816h(Bh0, Bh1, ahi[4 * kk], ahi[4 * kk + 1], ahi[4 * kk + 2], ahi[4 * kk + 3], bl0, bl1);
                mma16816h(Ch0, Ch1, alo[4 * kk], alo[4 * kk + 1], alo[4 * kk + 2], alo[4 * kk + 3], bh0, bh1);
            }
            const int col0 = n0 + 2 * cq;
            float2 b0f = h2f2(Bh0), b1f = h2f2(Bh1);
            float2 c0f = h2f2(Ch0), c1f = h2f2(Ch1);
            float z0 = (A0 + b0f.x + c0f.x) + p0[col0];
            float z1 = (A1 + b0f.y + c0f.y) + p0[col0 + 1];
            float z2 = (A2 + b1f.x + c1f.x) + p1[col0];
            float z3 = (A3 + b1f.y + c1f.y) + p1[col0 + 1];
            float o0 = __shfl_xor_sync(0xffffffffu, z0, 1);
            float o1 = __shfl_xor_sync(0xffffffffu, z1, 1);
            float o2 = __shfl_xor_sync(0xffffffffu, z2, 1);
            float o3 = __shfl_xor_sync(0xffffffffu, z3, 1);
            float zi = even ? z0 : o2;
            float zf = even ? z1 : o3;
            float zc = even ? o0 : z2;
            float zo = even ? o1 : z3;
            float cn = fsig(zf) * cS[jj] + fsig(zi) * tanha(zc);
            cS[jj] = cn;
            float hn = fsig(zo) * tanha(cn);
            const int u = 2 * (jbase + jj) + (cq >> 1);
            const int myrow = even ? R0l : R1l;
            __half hh = __float2half_rn(hn);
            __half hl = __float2half_rn(hn - __half2float(hh));
            *(__half*)(smb + SM_A + myrow * RSTRIDE + u * 2) = hh;
            *(__half*)(smb + SM_A + myrow * RSTRIDE + 224 + u * 2) = hl;
            const float* wp = sWops + u * NOPSN;
            pl[0] = fmaf(hn, wp[0], pl[0]);
            pl[1] = fmaf(hn, wp[1], pl[1]);
            pl[2] = fmaf(hn, wp[2], pl[2]);
            pl[3] = fmaf(hn, wp[3], pl[3]);
            pl[4] = fmaf(hn, wp[4], pl[4]);
        }

        #pragma unroll
        for (int n = 0; n < NOPSN; ++n)
            pl[n] += __shfl_xor_sync(0xffffffffu, pl[n], 2);
        if (cq < 2) {
            int rw = (cq == 0) ? R0l : R1l;
            #pragma unroll
            for (int n = 0; n < NOPSN; ++n)
                sPL[rw * 10 + nh * NOPSN + n] = pl[n];
        }
        pairbar(barid);   // bar2: slab sPL + h(t) complete

        if (epi) {
            int b = blockIdx.x * MROWS + erow;
            float lg[NOPSN];
            #pragma unroll
            for (int n = 0; n < NOPSN; ++n) {
                float s = sPL[erow * 10 + n] + sPL[erow * 10 + NOPSN + n];
                lg[n] = 1.5f * tanhf(s);
            }
            int op = 0;
            float best = 0.f, mx = lg[0], lsel = lg[0];
            #pragma unroll
            for (int n = 0; n < NOPSN; ++n) {
                float gum = -logf(-logf(un[n] + 1e-9f) + 1e-9f);
                float v = lg[n] + gum;
                if (n == 0) { best = v; }
                else if (v > best) { best = v; op = n; lsel = lg[n]; }
                if (lg[n] > mx) mx = lg[n];
            }
            float ss = 0.f;
            #pragma unroll
            for (int n = 0; n < NOPSN; ++n) ss += expf(lg[n] - mx);
            float lse = mx + logf(ss);
            float cur = lse - lsel;
            float ent = cur * expf(-cur);
            accLP += cur; accENT += ent;
            sOps[erow] = op;
            out[2 * (size_t)BB + (size_t)t * BB + b] = (float)op;
        }
    }

    if (epi) {
        int b = blockIdx.x * MROWS + erow;
        out[b] = accLP;
        out[BB + b] = accENT;
    }
}

extern "C" void kernel_launch(void* const* d_in, const int* in_sizes, int n_in,
                              void* d_out, int out_size) {
    const float* x0  = (const float*)d_in[0];
    const float* Wx  = (const float*)d_in[1];
    const float* Wh  = (const float*)d_in[2];
    const float* Wop = (const float*)d_in[3];
    const float* emb = (const float*)d_in[4];
    const float* u   = (const float*)d_in[5];
    float* out = (float*)d_out;

    cudaFuncSetAttribute(rnn_main, cudaFuncAttributeMaxDynamicSharedMemorySize, SM_TOTAL);
    rnn_main<<<BB / MROWS, NTHREADS, SM_TOTAL>>>(Wh, Wop, u, out, x0, Wx, emb);
}